// round 2
// baseline (speedup 1.0000x reference)
#include <cuda_runtime.h>
#include <math_constants.h>

// Problem constants
#define B_ 4
#define S_ 2048
#define E_ 1024
#define H_ 16
#define D_ 64

typedef unsigned long long u64;

// ---------- packed f32x2 helpers (B300: FFMA2 is the full-rate fp32 path) ----------
__device__ __forceinline__ u64 pack2(float lo, float hi) {
    u64 r; asm("mov.b64 %0, {%1,%2};" : "=l"(r) : "f"(lo), "f"(hi)); return r;
}
__device__ __forceinline__ void unpack2(u64 v, float& lo, float& hi) {
    asm("mov.b64 {%0,%1}, %2;" : "=f"(lo), "=f"(hi) : "l"(v));
}
__device__ __forceinline__ u64 fma2(u64 a, u64 b, u64 c) {
    u64 d; asm("fma.rn.f32x2 %0, %1, %2, %3;" : "=l"(d) : "l"(a), "l"(b), "l"(c)); return d;
}
__device__ __forceinline__ u64 mul2(u64 a, u64 b) {
    u64 d; asm("mul.rn.f32x2 %0, %1, %2;" : "=l"(d) : "l"(a), "l"(b)); return d;
}

// ---------- scratch (layout [B,H,S,D]) ----------
__device__ float g_Q[B_*H_*S_*D_];
__device__ float g_K[B_*H_*S_*D_];
__device__ float g_V[B_*H_*S_*D_];
__device__ float g_ctx[B_*H_*S_*D_];
__device__ float g_pooled[B_*E_];

// =====================================================================
// QKV projection:  Y = x @ W^T + b, output scattered to [B,H,S,D]
// M=8192, N=1024, K=1024. BM=BN=128, BK=8, 256 threads, 8x8 micro (f32x2 pairs over M)
// =====================================================================
__global__ __launch_bounds__(256) void qkv_kernel(
    const float* __restrict__ x,
    const float* __restrict__ Wq, const float* __restrict__ bq,
    const float* __restrict__ Wk, const float* __restrict__ bk,
    const float* __restrict__ Wv, const float* __restrict__ bv)
{
    __shared__ __align__(16) float As[8*128];
    __shared__ __align__(16) float Bs[8*128];

    const int z = blockIdx.z;
    const float* __restrict__ W    = (z == 0) ? Wq : ((z == 1) ? Wk : Wv);
    const float* __restrict__ bias = (z == 0) ? bq : ((z == 1) ? bk : bv);
    float* __restrict__ out        = (z == 0) ? g_Q : ((z == 1) ? g_K : g_V);

    const int tid = threadIdx.x;
    const int tx = tid & 15;       // 0..15 -> n micro
    const int ty = tid >> 4;       // 0..15 -> m micro
    const int m0 = blockIdx.y * 128;
    const int n0 = blockIdx.x * 128;

    const int lrow = tid >> 1;          // 0..127
    const int lk   = (tid & 1) * 4;     // 0 or 4

    u64 c2[4][8];
    #pragma unroll
    for (int ip = 0; ip < 4; ip++)
        #pragma unroll
        for (int j = 0; j < 8; j++) c2[ip][j] = 0ull;  // bits of (0.f,0.f)

    const float* xA = x + (size_t)(m0 + lrow) * E_ + lk;
    const float* wB = W + (size_t)(n0 + lrow) * E_ + lk;

    for (int k0 = 0; k0 < E_; k0 += 8) {
        float4 av = *(const float4*)(xA + k0);
        float4 bv4 = *(const float4*)(wB + k0);
        __syncthreads();
        As[(lk+0)*128 + lrow] = av.x;
        As[(lk+1)*128 + lrow] = av.y;
        As[(lk+2)*128 + lrow] = av.z;
        As[(lk+3)*128 + lrow] = av.w;
        Bs[(lk+0)*128 + lrow] = bv4.x;
        Bs[(lk+1)*128 + lrow] = bv4.y;
        Bs[(lk+2)*128 + lrow] = bv4.z;
        Bs[(lk+3)*128 + lrow] = bv4.w;
        __syncthreads();

        #pragma unroll
        for (int kk = 0; kk < 8; kk++) {
            ulonglong2 aA = *(const ulonglong2*)(As + kk*128 + ty*8);
            ulonglong2 aB = *(const ulonglong2*)(As + kk*128 + ty*8 + 4);
            u64 ap[4] = {aA.x, aA.y, aB.x, aB.y};
            float4 b0 = *(const float4*)(Bs + kk*128 + tx*8);
            float4 b1 = *(const float4*)(Bs + kk*128 + tx*8 + 4);
            float bn[8] = {b0.x,b0.y,b0.z,b0.w,b1.x,b1.y,b1.z,b1.w};
            #pragma unroll
            for (int j = 0; j < 8; j++) {
                u64 bd = pack2(bn[j], bn[j]);
                #pragma unroll
                for (int ip = 0; ip < 4; ip++)
                    c2[ip][j] = fma2(ap[ip], bd, c2[ip][j]);
            }
        }
    }

    // epilogue: add bias, scatter to [B,H,S,D]
    #pragma unroll
    for (int ip = 0; ip < 4; ip++) {
        float r0[8], r1[8];
        #pragma unroll
        for (int j = 0; j < 8; j++) unpack2(c2[ip][j], r0[j], r1[j]);
        #pragma unroll
        for (int r = 0; r < 2; r++) {
            const float* rr = r ? r1 : r0;
            int grow = m0 + ty*8 + 2*ip + r;
            int bb = grow >> 11;          // /S_
            int s  = grow & (S_ - 1);
            #pragma unroll
            for (int jq = 0; jq < 8; jq += 4) {
                int n = n0 + tx*8 + jq;
                int h = n >> 6, d = n & 63;
                float4 bv4 = *(const float4*)(bias + n);
                float4 v;
                v.x = rr[jq+0] + bv4.x;
                v.y = rr[jq+1] + bv4.y;
                v.z = rr[jq+2] + bv4.z;
                v.w = rr[jq+3] + bv4.w;
                *(float4*)(out + (size_t)((bb*H_ + h)*S_ + s) * D_ + d) = v;
            }
        }
    }
}

// =====================================================================
// Flash attention (fp32). One block per (b,h, 128-query tile).
// BLOCK_M=128, BLOCK_N=64, D=64. 256 threads: micro 8(m) x 4(n/d).
// Shared: Qs[d][128], Ks[d][64], Ps[n][128], Vs[n][64], mask[64] -> 98560 B dyn
// =====================================================================
#define ATTN_SMEM (((64*128) + (64*64) + (64*128) + (64*64)) * 4 + 64 * 4)

__global__ __launch_bounds__(256) void attn_kernel(const int* __restrict__ mask)
{
    extern __shared__ __align__(16) float smem[];
    float* Qs = smem;                  // [64][128] transposed, pre-scaled
    float* Ks = Qs + 64*128;           // [64][64] transposed
    float* Ps = Ks + 64*64;            // [64][128] P transposed (n-major)
    float* Vs = Ps + 64*128;           // [64][64] natural
    int*   smask = (int*)(Vs + 64*64); // [64]

    const int tid = threadIdx.x;
    const int tx = tid & 15;     // n/d micro (4 wide)
    const int ty = tid >> 4;     // m micro (8 tall)
    const int bh = blockIdx.y;
    const int b  = bh >> 4;
    const int m0 = blockIdx.x * 128;

    const float* Qg = g_Q + (size_t)(bh*S_ + m0) * D_;
    const float* Kg = g_K + (size_t)bh * S_ * D_;
    const float* Vg = g_V + (size_t)bh * S_ * D_;
    const float NEG_INF = -CUDART_INF_F;

    // load Q tile transposed, fold in 1/sqrt(D)
    #pragma unroll
    for (int it = 0; it < 8; it++) {
        int idx = tid + it*256;                 // 0..2047
        int r = idx >> 4, dq = (idx & 15) * 4;
        float4 v = *(const float4*)(Qg + r*64 + dq);
        Qs[(dq+0)*128 + r] = v.x * 0.125f;
        Qs[(dq+1)*128 + r] = v.y * 0.125f;
        Qs[(dq+2)*128 + r] = v.z * 0.125f;
        Qs[(dq+3)*128 + r] = v.w * 0.125f;
    }

    float mprev[8], lsum[8];
    #pragma unroll
    for (int i = 0; i < 8; i++) { mprev[i] = NEG_INF; lsum[i] = 0.f; }
    u64 o2[4][4];
    #pragma unroll
    for (int ip = 0; ip < 4; ip++)
        #pragma unroll
        for (int j = 0; j < 4; j++) o2[ip][j] = 0ull;

    for (int n0 = 0; n0 < S_; n0 += 64) {
        __syncthreads();   // previous PV done before overwriting tiles
        #pragma unroll
        for (int it = 0; it < 4; it++) {
            int idx = tid + it*256;             // 0..1023
            int r = idx >> 4, dq = (idx & 15) * 4;
            float4 kv = *(const float4*)(Kg + (size_t)(n0 + r)*64 + dq);
            Ks[(dq+0)*64 + r] = kv.x;
            Ks[(dq+1)*64 + r] = kv.y;
            Ks[(dq+2)*64 + r] = kv.z;
            Ks[(dq+3)*64 + r] = kv.w;
            float4 vv = *(const float4*)(Vg + (size_t)(n0 + r)*64 + dq);
            *(float4*)(Vs + r*64 + dq) = vv;
        }
        if (tid < 64) smask[tid] = mask[b*S_ + n0 + tid];
        __syncthreads();

        // ---- scores: S[m][n] = Q·K (Q pre-scaled) ----
        u64 sc2[4][4];
        #pragma unroll
        for (int ip = 0; ip < 4; ip++)
            #pragma unroll
            for (int j = 0; j < 4; j++) sc2[ip][j] = 0ull;

        #pragma unroll 8
        for (int d = 0; d < 64; d++) {
            ulonglong2 aA = *(const ulonglong2*)(Qs + d*128 + ty*8);
            ulonglong2 aB = *(const ulonglong2*)(Qs + d*128 + ty*8 + 4);
            float4 kb = *(const float4*)(Ks + d*64 + tx*4);
            u64 ap[4] = {aA.x, aA.y, aB.x, aB.y};
            float kn[4] = {kb.x, kb.y, kb.z, kb.w};
            #pragma unroll
            for (int j = 0; j < 4; j++) {
                u64 bd = pack2(kn[j], kn[j]);
                #pragma unroll
                for (int ip = 0; ip < 4; ip++)
                    sc2[ip][j] = fma2(ap[ip], bd, sc2[ip][j]);
            }
        }
        float sc[8][4];
        #pragma unroll
        for (int ip = 0; ip < 4; ip++)
            #pragma unroll
            for (int j = 0; j < 4; j++)
                unpack2(sc2[ip][j], sc[2*ip][j], sc[2*ip+1][j]);

        // ---- mask ----
        int mk[4];
        #pragma unroll
        for (int j = 0; j < 4; j++) mk[j] = smask[tx*4 + j];
        #pragma unroll
        for (int i = 0; i < 8; i++)
            #pragma unroll
            for (int j = 0; j < 4; j++)
                if (mk[j] == 0) sc[i][j] = NEG_INF;

        // ---- online softmax (row stats across 16 lanes sharing a row) ----
        float corr[8];
        #pragma unroll
        for (int i = 0; i < 8; i++) {
            float rm = fmaxf(fmaxf(sc[i][0], sc[i][1]), fmaxf(sc[i][2], sc[i][3]));
            rm = fmaxf(rm, __shfl_xor_sync(0xffffffffu, rm, 1));
            rm = fmaxf(rm, __shfl_xor_sync(0xffffffffu, rm, 2));
            rm = fmaxf(rm, __shfl_xor_sync(0xffffffffu, rm, 4));
            rm = fmaxf(rm, __shfl_xor_sync(0xffffffffu, rm, 8));
            float mn = fmaxf(mprev[i], rm);
            corr[i] = __expf(mprev[i] - mn);
            mprev[i] = mn;
            float rs = 0.f;
            #pragma unroll
            for (int j = 0; j < 4; j++) { sc[i][j] = __expf(sc[i][j] - mn); rs += sc[i][j]; }
            rs += __shfl_xor_sync(0xffffffffu, rs, 1);
            rs += __shfl_xor_sync(0xffffffffu, rs, 2);
            rs += __shfl_xor_sync(0xffffffffu, rs, 4);
            rs += __shfl_xor_sync(0xffffffffu, rs, 8);
            lsum[i] = lsum[i] * corr[i] + rs;
        }
        // rescale accumulated O
        #pragma unroll
        for (int ip = 0; ip < 4; ip++) {
            u64 cp = pack2(corr[2*ip], corr[2*ip+1]);
            #pragma unroll
            for (int j = 0; j < 4; j++) o2[ip][j] = mul2(o2[ip][j], cp);
        }
        // store P transposed (n-major) for conflict-free packed PV reads
        #pragma unroll
        for (int j = 0; j < 4; j++)
            #pragma unroll
            for (int i = 0; i < 8; i++)
                Ps[(tx*4 + j)*128 + ty*8 + i] = sc[i][j];
        __syncthreads();

        // ---- PV accumulate ----
        #pragma unroll 8
        for (int n = 0; n < 64; n++) {
            ulonglong2 pA = *(const ulonglong2*)(Ps + n*128 + ty*8);
            ulonglong2 pB = *(const ulonglong2*)(Ps + n*128 + ty*8 + 4);
            float4 vv = *(const float4*)(Vs + n*64 + tx*4);
            u64 pp[4] = {pA.x, pA.y, pB.x, pB.y};
            float vn[4] = {vv.x, vv.y, vv.z, vv.w};
            #pragma unroll
            for (int j = 0; j < 4; j++) {
                u64 vd = pack2(vn[j], vn[j]);
                #pragma unroll
                for (int ip = 0; ip < 4; ip++)
                    o2[ip][j] = fma2(pp[ip], vd, o2[ip][j]);
            }
        }
    }

    // epilogue: O /= l, write [B,H,S,D]
    float* Cg = g_ctx + (size_t)(bh*S_ + m0) * D_;
    #pragma unroll
    for (int ip = 0; ip < 4; ip++) {
        float e0[4], e1[4];
        #pragma unroll
        for (int j = 0; j < 4; j++) unpack2(o2[ip][j], e0[j], e1[j]);
        float inv0 = 1.f / lsum[2*ip];
        float inv1 = 1.f / lsum[2*ip + 1];
        float4 w0, w1;
        w0.x = e0[0]*inv0; w0.y = e0[1]*inv0; w0.z = e0[2]*inv0; w0.w = e0[3]*inv0;
        w1.x = e1[0]*inv1; w1.y = e1[1]*inv1; w1.z = e1[2]*inv1; w1.w = e1[3]*inv1;
        *(float4*)(Cg + (ty*8 + 2*ip + 0)*64 + tx*4) = w0;
        *(float4*)(Cg + (ty*8 + 2*ip + 1)*64 + tx*4) = w1;
    }
}

// =====================================================================
// Mean over S: pooled[b, h*64+d] = mean_s ctx[b,h,s,d]
// =====================================================================
__global__ __launch_bounds__(1024) void mean_kernel()
{
    __shared__ float sh[1024];
    const int bh = blockIdx.x;
    const int tid = threadIdx.x;
    const int d = tid & 63;
    const int c = tid >> 6;              // 0..15, 128 s each
    const float* base = g_ctx + (size_t)bh * S_ * D_;
    float sum = 0.f;
    const int s0 = c * 128;
    #pragma unroll 4
    for (int s = s0; s < s0 + 128; s++) sum += base[(size_t)s * 64 + d];
    sh[tid] = sum;
    __syncthreads();
    if (tid < 64) {
        float t = 0.f;
        #pragma unroll
        for (int k = 0; k < 16; k++) t += sh[tid + 64*k];
        int b = bh >> 4, h = bh & 15;
        g_pooled[b*E_ + h*64 + tid] = t * (1.0f / S_);
    }
}

// =====================================================================
// Head: o = pooled @ Wo^T + bo; o /= ||o||; u = o - text;
//       h = relu(u @ W1^T + b1); score = tanh(h @ W2^T + b2)
// One block per batch, 1024 threads.
// =====================================================================
__global__ __launch_bounds__(1024) void head_kernel(
    const float* __restrict__ text,
    const float* __restrict__ Wo, const float* __restrict__ bo,
    const float* __restrict__ W1, const float* __restrict__ b1,
    const float* __restrict__ W2, const float* __restrict__ b2,
    float* __restrict__ out)
{
    __shared__ float sp[1024];
    __shared__ float su[1024];
    __shared__ float red[32];
    __shared__ float s_inv;
    const int b = blockIdx.x;
    const int tid = threadIdx.x;

    sp[tid] = g_pooled[b*E_ + tid];
    __syncthreads();

    float acc = bo[tid];
    const float* wrow = Wo + (size_t)tid * E_;
    #pragma unroll 4
    for (int k = 0; k < E_; k += 4) {
        float4 w = *(const float4*)(wrow + k);
        acc += sp[k]*w.x + sp[k+1]*w.y + sp[k+2]*w.z + sp[k+3]*w.w;
    }

    float v = acc * acc;
    #pragma unroll
    for (int off = 16; off > 0; off >>= 1) v += __shfl_xor_sync(0xffffffffu, v, off);
    if ((tid & 31) == 0) red[tid >> 5] = v;
    __syncthreads();
    if (tid < 32) {
        float t = red[tid];
        #pragma unroll
        for (int off = 16; off > 0; off >>= 1) t += __shfl_xor_sync(0xffffffffu, t, off);
        if (tid == 0) s_inv = rsqrtf(t);
    }
    __syncthreads();

    su[tid] = acc * s_inv - text[b*E_ + tid];
    __syncthreads();

    float part = 0.f;
    if (tid < 512) {
        float h = b1[tid];
        const float* w1row = W1 + (size_t)tid * E_;
        #pragma unroll 4
        for (int k = 0; k < E_; k += 4) {
            float4 w = *(const float4*)(w1row + k);
            h += su[k]*w.x + su[k+1]*w.y + su[k+2]*w.z + su[k+3]*w.w;
        }
        h = fmaxf(h, 0.f);
        part = h * W2[tid];
    }
    #pragma unroll
    for (int off = 16; off > 0; off >>= 1) part += __shfl_xor_sync(0xffffffffu, part, off);
    if ((tid & 31) == 0) red[tid >> 5] = part;
    __syncthreads();
    if (tid < 32) {
        float t = red[tid];
        #pragma unroll
        for (int off = 16; off > 0; off >>= 1) t += __shfl_xor_sync(0xffffffffu, t, off);
        if (tid == 0) out[b] = tanhf(t + b2[0]);
    }
}

// =====================================================================
// Launch
// =====================================================================
extern "C" void kernel_launch(void* const* d_in, const int* in_sizes, int n_in,
                              void* d_out, int out_size)
{
    (void)in_sizes; (void)n_in; (void)out_size;
    const float* x    = (const float*)d_in[0];
    const int*   mask = (const int*)  d_in[1];
    const float* text = (const float*)d_in[2];
    const float* Wq = (const float*)d_in[3];
    const float* bq = (const float*)d_in[4];
    const float* Wk = (const float*)d_in[5];
    const float* bk = (const float*)d_in[6];
    const float* Wv = (const float*)d_in[7];
    const float* bv = (const float*)d_in[8];
    const float* Wo = (const float*)d_in[9];
    const float* bo = (const float*)d_in[10];
    const float* W1 = (const float*)d_in[11];
    const float* b1 = (const float*)d_in[12];
    const float* W2 = (const float*)d_in[13];
    const float* b2 = (const float*)d_in[14];
    float* out = (float*)d_out;

    cudaFuncSetAttribute(attn_kernel, cudaFuncAttributeMaxDynamicSharedMemorySize, ATTN_SMEM);

    qkv_kernel<<<dim3(8, 64, 3), 256>>>(x, Wq, bq, Wk, bk, Wv, bv);
    attn_kernel<<<dim3(16, 64), 256, ATTN_SMEM>>>(mask);
    mean_kernel<<<64, 1024>>>();
    head_kernel<<<4, 1024>>>(text, Wo, bo, W1, b1, W2, b2, out);
}

// round 3
// speedup vs baseline: 3.4460x; 3.4460x over previous
#include <cuda_runtime.h>

// Problem constants
#define B_ 4
#define S_ 2048
#define E_ 1024
#define H_ 16
#define D_ 64

// ---------------- scratch ----------------
__device__ float g_Q[B_*H_*S_*D_];     // [B,H,S,D]
__device__ float g_K[B_*H_*S_*D_];
__device__ float g_V[B_*H_*S_*D_];
__device__ float g_pooled[B_*E_];      // column sums of attention output (pre mean-scale)
__device__ float g_o[B_*E_];           // out_proj output
__device__ float g_nrm[B_];            // squared norms
__device__ float g_score[B_];          // pre-tanh score

// ---------------- helpers ----------------
__device__ __forceinline__ unsigned f2tf(float x) {
    unsigned r; asm("cvt.rna.tf32.f32 %0, %1;" : "=r"(r) : "f"(x)); return r;
}
__device__ __forceinline__ float f2tff(float x) { return __uint_as_float(f2tf(x)); }

// D += A(m16k8,row) * B(k8n8,col), tf32
__device__ __forceinline__ void mma8(float* c, const unsigned* a, const unsigned* b) {
    asm("mma.sync.aligned.m16n8k8.row.col.f32.tf32.tf32.f32 "
        "{%0,%1,%2,%3}, {%4,%5,%6,%7}, {%8,%9}, {%0,%1,%2,%3};"
        : "+f"(c[0]), "+f"(c[1]), "+f"(c[2]), "+f"(c[3])
        : "r"(a[0]), "r"(a[1]), "r"(a[2]), "r"(a[3]), "r"(b[0]), "r"(b[1]));
}

// fast exp on the FMA/ALU pipes (input must already be clamped to [-80, 60])
__device__ __forceinline__ float exp_fast(float s) {
    float y = s * 1.4426950408889634f;
    float t = y + 12582912.f;             // round-to-nearest int via magic number
    float n = t - 12582912.f;
    float f = y - n;                      // f in [-0.5, 0.5]
    float p = fmaf(fmaf(fmaf(fmaf(0.009618130f, f,
                    0.05550411f), f, 0.2401597f), f, 0.6931472f), f, 1.0f);
    return __int_as_float(__float_as_int(p) + (__float_as_int(t) << 23));
}
// truncate fp32 to tf32 bit pattern (keeps P consistent between lsum and PV mma)
__device__ __forceinline__ float tf_trunc(float x) {
    return __uint_as_float(__float_as_uint(x) & 0xffffe000u);
}

// =====================================================================
// zero scratch accumulators
// =====================================================================
__global__ void zero_kernel() {
    int i = blockIdx.x * blockDim.x + threadIdx.x;
    if (i < B_*E_) g_pooled[i] = 0.f;
    if (i < B_) { g_nrm[i] = 0.f; g_score[i] = 0.f; }
}

// =====================================================================
// QKV projection via tf32 mma: Y = x @ W^T + b, scatter to [B,H,S,D]
// M=8192 N=1024 K=1024. BM=128 BN=128 BK=32, 256 threads (8 warps, 2x4),
// warp tile 64x32 (mt=4, nt=4).
// =====================================================================
__global__ __launch_bounds__(256) void qkv_mma(
    const float* __restrict__ x,
    const float* __restrict__ Wq, const float* __restrict__ bq,
    const float* __restrict__ Wk, const float* __restrict__ bk,
    const float* __restrict__ Wv, const float* __restrict__ bv)
{
    __shared__ __align__(16) float As[128][36];   // [m][k], pad->bank 4r+c conflict-free
    __shared__ __align__(16) float Bs[128][36];   // [n][k]

    const int z = blockIdx.z;
    const float* __restrict__ W    = (z == 0) ? Wq : ((z == 1) ? Wk : Wv);
    const float* __restrict__ bias = (z == 0) ? bq : ((z == 1) ? bk : bv);
    float* __restrict__ out        = (z == 0) ? g_Q : ((z == 1) ? g_K : g_V);

    const int tid  = threadIdx.x;
    const int lane = tid & 31, wid = tid >> 5;
    const int wm = wid >> 2, wn = wid & 3;
    const int m0 = blockIdx.y * 128, n0 = blockIdx.x * 128;
    const int r = lane >> 2, c = lane & 3;

    float acc[4][4][4];
    #pragma unroll
    for (int mt = 0; mt < 4; mt++)
        #pragma unroll
        for (int nt = 0; nt < 4; nt++)
            #pragma unroll
            for (int j = 0; j < 4; j++) acc[mt][nt][j] = 0.f;

    const int lr  = tid >> 3;         // 0..31
    const int lc4 = (tid & 7) * 4;    // 0..28

    for (int k0 = 0; k0 < E_; k0 += 32) {
        __syncthreads();
        #pragma unroll
        for (int it = 0; it < 4; it++) {
            int rr = lr + it * 32;
            float4 va = *(const float4*)(x + (size_t)(m0 + rr) * E_ + k0 + lc4);
            float4 vb = *(const float4*)(W + (size_t)(n0 + rr) * E_ + k0 + lc4);
            float4 sa, sb;
            sa.x = f2tff(va.x); sa.y = f2tff(va.y); sa.z = f2tff(va.z); sa.w = f2tff(va.w);
            sb.x = f2tff(vb.x); sb.y = f2tff(vb.y); sb.z = f2tff(vb.z); sb.w = f2tff(vb.w);
            *(float4*)&As[rr][lc4] = sa;
            *(float4*)&Bs[rr][lc4] = sb;
        }
        __syncthreads();

        #pragma unroll
        for (int ks = 0; ks < 4; ks++) {
            unsigned a[4][4];
            #pragma unroll
            for (int mt = 0; mt < 4; mt++) {
                int row = wm * 64 + mt * 16;
                a[mt][0] = __float_as_uint(As[row + r    ][ks*8 + c    ]);
                a[mt][1] = __float_as_uint(As[row + r + 8][ks*8 + c    ]);
                a[mt][2] = __float_as_uint(As[row + r    ][ks*8 + c + 4]);
                a[mt][3] = __float_as_uint(As[row + r + 8][ks*8 + c + 4]);
            }
            #pragma unroll
            for (int nt = 0; nt < 4; nt++) {
                int col = wn * 32 + nt * 8;
                unsigned bf[2];
                bf[0] = __float_as_uint(Bs[col + r][ks*8 + c    ]);
                bf[1] = __float_as_uint(Bs[col + r][ks*8 + c + 4]);
                #pragma unroll
                for (int mt = 0; mt < 4; mt++) mma8(acc[mt][nt], a[mt], bf);
            }
        }
    }

    // epilogue: bias + scatter to [B,H,S,D]
    #pragma unroll
    for (int nt = 0; nt < 4; nt++) {
        int coln = n0 + wn * 32 + nt * 8 + 2 * c;
        int h = coln >> 6, d = coln & 63;
        float bv0 = bias[coln], bv1 = bias[coln + 1];
        #pragma unroll
        for (int mt = 0; mt < 4; mt++) {
            int gm = m0 + wm * 64 + mt * 16 + r;
            int bb = gm >> 11, s = gm & (S_ - 1);
            float2 v0 = make_float2(acc[mt][nt][0] + bv0, acc[mt][nt][1] + bv1);
            float2 v1 = make_float2(acc[mt][nt][2] + bv0, acc[mt][nt][3] + bv1);
            *(float2*)(out + (size_t)((bb*H_ + h)*S_ + s    ) * D_ + d) = v0;
            *(float2*)(out + (size_t)((bb*H_ + h)*S_ + s + 8) * D_ + d) = v1;
        }
    }
}

// =====================================================================
// Flash attention via tf32 mma, no-max softmax with polynomial exp.
// Block: 256 query rows (8 warps x 32 rows, mt=2), key tile 64.
// Fuses the mean-over-S via atomicAdd into g_pooled.
// =====================================================================
#define AT_ST 68    // padded row stride -> banks 4r+c, conflict-free frag loads
#define ATTN_SMEM ((256 + 64 + 64 + 256) * AT_ST * 4 + 64 * 4)

__global__ __launch_bounds__(256) void attn_mma(const int* __restrict__ mask)
{
    extern __shared__ __align__(16) float sm[];
    float* Qs = sm;                        // [256][AT_ST] tf32, pre-scaled
    float* Ks = Qs + 256 * AT_ST;          // [64][AT_ST]  tf32
    float* Vs = Ks + 64 * AT_ST;           // [64][AT_ST]  tf32
    float* Ps = Vs + 64 * AT_ST;           // [256][AT_ST] tf32 (truncated exp)
    float* smf = Ps + 256 * AT_ST;         // [64] mask add (-1e9 / 0)

    const int tid  = threadIdx.x;
    const int lane = tid & 31, wid = tid >> 5;
    const int bh = blockIdx.y, b = bh >> 4;
    const int m0 = blockIdx.x * 256;
    const int r = lane >> 2, c = lane & 3;
    const int wrow = wid * 32;

    const float* Qg = g_Q + (size_t)(bh * S_ + m0) * D_;
    const float* Kg = g_K + (size_t)bh * S_ * D_;
    const float* Vg = g_V + (size_t)bh * S_ * D_;

    // Q tile (fold 1/sqrt(D), convert tf32)
    #pragma unroll
    for (int it = 0; it < 16; it++) {
        int lin = tid + it * 256;
        int rr = lin >> 4, c4 = (lin & 15) * 4;
        float4 v = *(const float4*)(Qg + (size_t)rr * D_ + c4);
        float4 sv;
        sv.x = f2tff(v.x * 0.125f); sv.y = f2tff(v.y * 0.125f);
        sv.z = f2tff(v.z * 0.125f); sv.w = f2tff(v.w * 0.125f);
        *(float4*)&Qs[rr * AT_ST + c4] = sv;
    }

    float oac[2][8][4];
    #pragma unroll
    for (int mt = 0; mt < 2; mt++)
        #pragma unroll
        for (int dt = 0; dt < 8; dt++)
            #pragma unroll
            for (int j = 0; j < 4; j++) oac[mt][dt][j] = 0.f;
    float lsum[2][2] = {{0.f, 0.f}, {0.f, 0.f}};

    for (int n0 = 0; n0 < S_; n0 += 64) {
        __syncthreads();
        #pragma unroll
        for (int it = 0; it < 4; it++) {
            int lin = tid + it * 256;
            int rr = lin >> 4, c4 = (lin & 15) * 4;
            float4 kv = *(const float4*)(Kg + (size_t)(n0 + rr) * D_ + c4);
            float4 vv = *(const float4*)(Vg + (size_t)(n0 + rr) * D_ + c4);
            float4 sk, sv;
            sk.x = f2tff(kv.x); sk.y = f2tff(kv.y); sk.z = f2tff(kv.z); sk.w = f2tff(kv.w);
            sv.x = f2tff(vv.x); sv.y = f2tff(vv.y); sv.z = f2tff(vv.z); sv.w = f2tff(vv.w);
            *(float4*)&Ks[rr * AT_ST + c4] = sk;
            *(float4*)&Vs[rr * AT_ST + c4] = sv;
        }
        if (tid < 64) smf[tid] = mask[b * S_ + n0 + tid] ? 0.f : -1e9f;
        __syncthreads();

        // ---- S = Q K^T ----
        float sc[2][8][4];
        #pragma unroll
        for (int mt = 0; mt < 2; mt++)
            #pragma unroll
            for (int nt = 0; nt < 8; nt++)
                #pragma unroll
                for (int j = 0; j < 4; j++) sc[mt][nt][j] = 0.f;

        #pragma unroll
        for (int ks = 0; ks < 8; ks++) {
            unsigned a[2][4];
            #pragma unroll
            for (int mt = 0; mt < 2; mt++) {
                int row = wrow + mt * 16;
                a[mt][0] = __float_as_uint(Qs[(row + r    ) * AT_ST + ks*8 + c    ]);
                a[mt][1] = __float_as_uint(Qs[(row + r + 8) * AT_ST + ks*8 + c    ]);
                a[mt][2] = __float_as_uint(Qs[(row + r    ) * AT_ST + ks*8 + c + 4]);
                a[mt][3] = __float_as_uint(Qs[(row + r + 8) * AT_ST + ks*8 + c + 4]);
            }
            #pragma unroll
            for (int nt = 0; nt < 8; nt++) {
                unsigned bf[2];
                bf[0] = __float_as_uint(Ks[(nt*8 + r) * AT_ST + ks*8 + c    ]);
                bf[1] = __float_as_uint(Ks[(nt*8 + r) * AT_ST + ks*8 + c + 4]);
                mma8(sc[0][nt], a[0], bf);
                mma8(sc[1][nt], a[1], bf);
            }
        }

        // ---- exp (poly, FMA pipe), accumulate row sums, truncate to tf32 ----
        #pragma unroll
        for (int nt = 0; nt < 8; nt++) {
            float mf0 = smf[nt*8 + 2*c];
            float mf1 = smf[nt*8 + 2*c + 1];
            #pragma unroll
            for (int mt = 0; mt < 2; mt++) {
                float e0 = tf_trunc(exp_fast(fminf(fmaxf(sc[mt][nt][0] + mf0, -80.f), 60.f)));
                float e1 = tf_trunc(exp_fast(fminf(fmaxf(sc[mt][nt][1] + mf1, -80.f), 60.f)));
                float e2 = tf_trunc(exp_fast(fminf(fmaxf(sc[mt][nt][2] + mf0, -80.f), 60.f)));
                float e3 = tf_trunc(exp_fast(fminf(fmaxf(sc[mt][nt][3] + mf1, -80.f), 60.f)));
                lsum[mt][0] += e0 + e1;
                lsum[mt][1] += e2 + e3;
                sc[mt][nt][0] = e0; sc[mt][nt][1] = e1;
                sc[mt][nt][2] = e2; sc[mt][nt][3] = e3;
            }
        }

        // ---- P to smem (warp-private rows) ----
        #pragma unroll
        for (int mt = 0; mt < 2; mt++) {
            int row = wrow + mt * 16;
            #pragma unroll
            for (int nt = 0; nt < 8; nt++) {
                *(float2*)&Ps[(row + r    ) * AT_ST + nt*8 + 2*c] =
                    make_float2(sc[mt][nt][0], sc[mt][nt][1]);
                *(float2*)&Ps[(row + r + 8) * AT_ST + nt*8 + 2*c] =
                    make_float2(sc[mt][nt][2], sc[mt][nt][3]);
            }
        }
        __syncwarp();

        // ---- O += P V ----
        #pragma unroll
        for (int ks = 0; ks < 8; ks++) {
            unsigned a[2][4];
            #pragma unroll
            for (int mt = 0; mt < 2; mt++) {
                int row = wrow + mt * 16;
                a[mt][0] = __float_as_uint(Ps[(row + r    ) * AT_ST + ks*8 + c    ]);
                a[mt][1] = __float_as_uint(Ps[(row + r + 8) * AT_ST + ks*8 + c    ]);
                a[mt][2] = __float_as_uint(Ps[(row + r    ) * AT_ST + ks*8 + c + 4]);
                a[mt][3] = __float_as_uint(Ps[(row + r + 8) * AT_ST + ks*8 + c + 4]);
            }
            #pragma unroll
            for (int dt = 0; dt < 8; dt++) {
                unsigned bf[2];
                bf[0] = __float_as_uint(Vs[(ks*8 + c    ) * AT_ST + dt*8 + r]);
                bf[1] = __float_as_uint(Vs[(ks*8 + c + 4) * AT_ST + dt*8 + r]);
                mma8(oac[0][dt], a[0], bf);
                mma8(oac[1][dt], a[1], bf);
            }
        }
    }

    // ---- epilogue: normalize rows, fused mean via atomics ----
    #pragma unroll
    for (int mt = 0; mt < 2; mt++)
        #pragma unroll
        for (int j = 0; j < 2; j++) {
            float v = lsum[mt][j];
            v += __shfl_xor_sync(0xffffffffu, v, 1);
            v += __shfl_xor_sync(0xffffffffu, v, 2);
            lsum[mt][j] = 1.f / v;
        }

    const int h = bh & 15;
    #pragma unroll
    for (int dt = 0; dt < 8; dt++) {
        float p0 = oac[0][dt][0]*lsum[0][0] + oac[0][dt][2]*lsum[0][1]
                 + oac[1][dt][0]*lsum[1][0] + oac[1][dt][2]*lsum[1][1];
        float p1 = oac[0][dt][1]*lsum[0][0] + oac[0][dt][3]*lsum[0][1]
                 + oac[1][dt][1]*lsum[1][0] + oac[1][dt][3]*lsum[1][1];
        p0 += __shfl_xor_sync(0xffffffffu, p0, 4);
        p0 += __shfl_xor_sync(0xffffffffu, p0, 8);
        p0 += __shfl_xor_sync(0xffffffffu, p0, 16);
        p1 += __shfl_xor_sync(0xffffffffu, p1, 4);
        p1 += __shfl_xor_sync(0xffffffffu, p1, 8);
        p1 += __shfl_xor_sync(0xffffffffu, p1, 16);
        if (lane < 4) {
            atomicAdd(&g_pooled[b*E_ + h*64 + dt*8 + 2*c    ], p0);
            atomicAdd(&g_pooled[b*E_ + h*64 + dt*8 + 2*c + 1], p1);
        }
    }
}

// =====================================================================
// head A: o = (pooled/S) @ Wo^T + bo ; accumulate squared norm
// grid (128, B), 256 thr; warp per output column
// =====================================================================
__global__ __launch_bounds__(256) void headA_kernel(
    const float* __restrict__ Wo, const float* __restrict__ bo)
{
    const int b = blockIdx.y;
    const int n = blockIdx.x * 8 + (threadIdx.x >> 5);
    const int lane = threadIdx.x & 31;
    const float* pr = g_pooled + b * E_;
    const float* wr = Wo + (size_t)n * E_;
    float acc = 0.f;
    #pragma unroll
    for (int i = 0; i < 8; i++) {
        int k = i * 128 + lane * 4;
        float4 w = *(const float4*)(wr + k);
        float4 p = *(const float4*)(pr + k);
        acc += p.x*w.x + p.y*w.y + p.z*w.z + p.w*w.w;
    }
    #pragma unroll
    for (int off = 16; off > 0; off >>= 1)
        acc += __shfl_xor_sync(0xffffffffu, acc, off);
    if (lane == 0) {
        float o = acc * (1.0f / S_) + bo[n];
        g_o[b * E_ + n] = o;
        atomicAdd(&g_nrm[b], o * o);
    }
}

// =====================================================================
// head B: u = o/||o|| - text ; h = relu(u @ W1^T + b1) ; score += h*W2
// grid (64, B), 256 thr; warp per hidden row
// =====================================================================
__global__ __launch_bounds__(256) void headB_kernel(
    const float* __restrict__ text,
    const float* __restrict__ W1, const float* __restrict__ b1,
    const float* __restrict__ W2)
{
    const int b = blockIdx.y;
    const int rr = blockIdx.x * 8 + (threadIdx.x >> 5);
    const int lane = threadIdx.x & 31;
    const float rinv = rsqrtf(g_nrm[b]);
    const float* orow = g_o + b * E_;
    const float* trow = text + b * E_;
    const float* wr = W1 + (size_t)rr * E_;
    float acc = 0.f;
    #pragma unroll
    for (int i = 0; i < 8; i++) {
        int k = i * 128 + lane * 4;
        float4 w = *(const float4*)(wr + k);
        float4 o = *(const float4*)(orow + k);
        float4 t = *(const float4*)(trow + k);
        acc += (o.x*rinv - t.x)*w.x + (o.y*rinv - t.y)*w.y
             + (o.z*rinv - t.z)*w.z + (o.w*rinv - t.w)*w.w;
    }
    #pragma unroll
    for (int off = 16; off > 0; off >>= 1)
        acc += __shfl_xor_sync(0xffffffffu, acc, off);
    if (lane == 0) {
        float hv = fmaxf(acc + b1[rr], 0.f);
        atomicAdd(&g_score[b], hv * W2[rr]);
    }
}

__global__ void headC_kernel(const float* __restrict__ b2, float* __restrict__ out)
{
    int i = threadIdx.x;
    if (i < B_) out[i] = tanhf(g_score[i] + b2[0]);
}

// =====================================================================
// Launch
// =====================================================================
extern "C" void kernel_launch(void* const* d_in, const int* in_sizes, int n_in,
                              void* d_out, int out_size)
{
    (void)in_sizes; (void)n_in; (void)out_size;
    const float* x    = (const float*)d_in[0];
    const int*   mask = (const int*)  d_in[1];
    const float* text = (const float*)d_in[2];
    const float* Wq = (const float*)d_in[3];
    const float* bq = (const float*)d_in[4];
    const float* Wk = (const float*)d_in[5];
    const float* bk = (const float*)d_in[6];
    const float* Wv = (const float*)d_in[7];
    const float* bv = (const float*)d_in[8];
    const float* Wo = (const float*)d_in[9];
    const float* bo = (const float*)d_in[10];
    const float* W1 = (const float*)d_in[11];
    const float* b1 = (const float*)d_in[12];
    const float* W2 = (const float*)d_in[13];
    const float* b2 = (const float*)d_in[14];
    float* out = (float*)d_out;

    cudaFuncSetAttribute(attn_mma, cudaFuncAttributeMaxDynamicSharedMemorySize, ATTN_SMEM);

    zero_kernel<<<16, 256>>>();
    qkv_mma<<<dim3(8, 64, 3), 256>>>(x, Wq, bq, Wk, bk, Wv, bv);
    attn_mma<<<dim3(8, 64), 256, ATTN_SMEM>>>(mask);
    headA_kernel<<<dim3(128, B_), 256>>>(Wo, bo);
    headB_kernel<<<dim3(64, B_), 256>>>(text, W1, b1, W2);
    headC_kernel<<<1, 32>>>(b2, out);
}

// round 4
// speedup vs baseline: 3.4470x; 1.0003x over previous
#include <cuda_runtime.h>

// Problem constants
#define B_ 4
#define S_ 2048
#define E_ 1024
#define H_ 16
#define D_ 64

// ---------------- scratch ----------------
__device__ float g_Q[B_*H_*S_*D_];     // [B,H,S,D]
__device__ float g_K[B_*H_*S_*D_];
__device__ float g_V[B_*H_*S_*D_];
__device__ float g_pooled[B_*E_];      // column sums of attention output (pre mean-scale)
__device__ float g_o[B_*E_];           // out_proj output
__device__ float g_nrm[B_];            // squared norms
__device__ float g_score[B_];          // pre-tanh score

// ---------------- helpers ----------------
__device__ __forceinline__ unsigned f2tf(float x) {
    unsigned r; asm("cvt.rna.tf32.f32 %0, %1;" : "=r"(r) : "f"(x)); return r;
}
__device__ __forceinline__ float f2tff(float x) { return __uint_as_float(f2tf(x)); }

// D += A(m16k8,row) * B(k8n8,col), tf32
__device__ __forceinline__ void mma8(float* c, const unsigned* a, const unsigned* b) {
    asm("mma.sync.aligned.m16n8k8.row.col.f32.tf32.tf32.f32 "
        "{%0,%1,%2,%3}, {%4,%5,%6,%7}, {%8,%9}, {%0,%1,%2,%3};"
        : "+f"(c[0]), "+f"(c[1]), "+f"(c[2]), "+f"(c[3])
        : "r"(a[0]), "r"(a[1]), "r"(a[2]), "r"(a[3]), "r"(b[0]), "r"(b[1]));
}

// fast exp on the FMA/ALU pipes (input must already be clamped to [-80, 60])
__device__ __forceinline__ float exp_fast(float s) {
    float y = s * 1.4426950408889634f;
    float t = y + 12582912.f;             // round-to-nearest int via magic number
    float n = t - 12582912.f;
    float f = y - n;                      // f in [-0.5, 0.5]
    float p = fmaf(fmaf(fmaf(fmaf(0.009618130f, f,
                    0.05550411f), f, 0.2401597f), f, 0.6931472f), f, 1.0f);
    return __int_as_float(__float_as_int(p) + (__float_as_int(t) << 23));
}
// truncate fp32 to tf32 bit pattern (keeps P consistent between lsum and PV mma)
__device__ __forceinline__ float tf_trunc(float x) {
    return __uint_as_float(__float_as_uint(x) & 0xffffe000u);
}

// =====================================================================
// zero scratch accumulators
// =====================================================================
__global__ void zero_kernel() {
    int i = blockIdx.x * blockDim.x + threadIdx.x;
    if (i < B_*E_) g_pooled[i] = 0.f;
    if (i < B_) { g_nrm[i] = 0.f; g_score[i] = 0.f; }
}

// =====================================================================
// QKV projection via tf32 mma: Y = x @ W^T + b, scatter to [B,H,S,D]
// M=8192 N=1024 K=1024. BM=128 BN=128 BK=32, 256 threads (8 warps, 2x4),
// warp tile 64x32 (mt=4, nt=4).
// =====================================================================
__global__ __launch_bounds__(256) void qkv_mma(
    const float* __restrict__ x,
    const float* __restrict__ Wq, const float* __restrict__ bq,
    const float* __restrict__ Wk, const float* __restrict__ bk,
    const float* __restrict__ Wv, const float* __restrict__ bv)
{
    __shared__ __align__(16) float As[128][36];   // [m][k], pad->bank 4r+c conflict-free
    __shared__ __align__(16) float Bs[128][36];   // [n][k]

    const int z = blockIdx.z;
    const float* __restrict__ W    = (z == 0) ? Wq : ((z == 1) ? Wk : Wv);
    const float* __restrict__ bias = (z == 0) ? bq : ((z == 1) ? bk : bv);
    float* __restrict__ out        = (z == 0) ? g_Q : ((z == 1) ? g_K : g_V);

    const int tid  = threadIdx.x;
    const int lane = tid & 31, wid = tid >> 5;
    const int wm = wid >> 2, wn = wid & 3;
    const int m0 = blockIdx.y * 128, n0 = blockIdx.x * 128;
    const int r = lane >> 2, c = lane & 3;

    float acc[4][4][4];
    #pragma unroll
    for (int mt = 0; mt < 4; mt++)
        #pragma unroll
        for (int nt = 0; nt < 4; nt++)
            #pragma unroll
            for (int j = 0; j < 4; j++) acc[mt][nt][j] = 0.f;

    const int lr  = tid >> 3;         // 0..31
    const int lc4 = (tid & 7) * 4;    // 0..28

    for (int k0 = 0; k0 < E_; k0 += 32) {
        __syncthreads();
        #pragma unroll
        for (int it = 0; it < 4; it++) {
            int rr = lr + it * 32;
            float4 va = *(const float4*)(x + (size_t)(m0 + rr) * E_ + k0 + lc4);
            float4 vb = *(const float4*)(W + (size_t)(n0 + rr) * E_ + k0 + lc4);
            float4 sa, sb;
            sa.x = f2tff(va.x); sa.y = f2tff(va.y); sa.z = f2tff(va.z); sa.w = f2tff(va.w);
            sb.x = f2tff(vb.x); sb.y = f2tff(vb.y); sb.z = f2tff(vb.z); sb.w = f2tff(vb.w);
            *(float4*)&As[rr][lc4] = sa;
            *(float4*)&Bs[rr][lc4] = sb;
        }
        __syncthreads();

        #pragma unroll
        for (int ks = 0; ks < 4; ks++) {
            unsigned a[4][4];
            #pragma unroll
            for (int mt = 0; mt < 4; mt++) {
                int row = wm * 64 + mt * 16;
                a[mt][0] = __float_as_uint(As[row + r    ][ks*8 + c    ]);
                a[mt][1] = __float_as_uint(As[row + r + 8][ks*8 + c    ]);
                a[mt][2] = __float_as_uint(As[row + r    ][ks*8 + c + 4]);
                a[mt][3] = __float_as_uint(As[row + r + 8][ks*8 + c + 4]);
            }
            #pragma unroll
            for (int nt = 0; nt < 4; nt++) {
                int col = wn * 32 + nt * 8;
                unsigned bf[2];
                bf[0] = __float_as_uint(Bs[col + r][ks*8 + c    ]);
                bf[1] = __float_as_uint(Bs[col + r][ks*8 + c + 4]);
                #pragma unroll
                for (int mt = 0; mt < 4; mt++) mma8(acc[mt][nt], a[mt], bf);
            }
        }
    }

    // epilogue: bias + scatter to [B,H,S,D]
    #pragma unroll
    for (int nt = 0; nt < 4; nt++) {
        int coln = n0 + wn * 32 + nt * 8 + 2 * c;
        int h = coln >> 6, d = coln & 63;
        float bv0 = bias[coln], bv1 = bias[coln + 1];
        #pragma unroll
        for (int mt = 0; mt < 4; mt++) {
            int gm = m0 + wm * 64 + mt * 16 + r;
            int bb = gm >> 11, s = gm & (S_ - 1);
            float2 v0 = make_float2(acc[mt][nt][0] + bv0, acc[mt][nt][1] + bv1);
            float2 v1 = make_float2(acc[mt][nt][2] + bv0, acc[mt][nt][3] + bv1);
            *(float2*)(out + (size_t)((bb*H_ + h)*S_ + s    ) * D_ + d) = v0;
            *(float2*)(out + (size_t)((bb*H_ + h)*S_ + s + 8) * D_ + d) = v1;
        }
    }
}

// =====================================================================
// Flash attention via tf32 mma, no-max softmax with polynomial exp.
// Block: 256 query rows (8 warps x 32 rows, mt=2), key tile 64.
// Fuses the mean-over-S via atomicAdd into g_pooled.
// =====================================================================
#define AT_ST 68    // padded row stride -> banks 4r+c, conflict-free frag loads
#define ATTN_SMEM ((256 + 64 + 64 + 256) * AT_ST * 4 + 64 * 4)

__global__ __launch_bounds__(256) void attn_mma(const int* __restrict__ mask)
{
    extern __shared__ __align__(16) float sm[];
    float* Qs = sm;                        // [256][AT_ST] tf32, pre-scaled
    float* Ks = Qs + 256 * AT_ST;          // [64][AT_ST]  tf32
    float* Vs = Ks + 64 * AT_ST;           // [64][AT_ST]  tf32
    float* Ps = Vs + 64 * AT_ST;           // [256][AT_ST] tf32 (truncated exp)
    float* smf = Ps + 256 * AT_ST;         // [64] mask add (-1e9 / 0)

    const int tid  = threadIdx.x;
    const int lane = tid & 31, wid = tid >> 5;
    const int bh = blockIdx.y, b = bh >> 4;
    const int m0 = blockIdx.x * 256;
    const int r = lane >> 2, c = lane & 3;
    const int wrow = wid * 32;

    const float* Qg = g_Q + (size_t)(bh * S_ + m0) * D_;
    const float* Kg = g_K + (size_t)bh * S_ * D_;
    const float* Vg = g_V + (size_t)bh * S_ * D_;

    // Q tile (fold 1/sqrt(D), convert tf32)
    #pragma unroll
    for (int it = 0; it < 16; it++) {
        int lin = tid + it * 256;
        int rr = lin >> 4, c4 = (lin & 15) * 4;
        float4 v = *(const float4*)(Qg + (size_t)rr * D_ + c4);
        float4 sv;
        sv.x = f2tff(v.x * 0.125f); sv.y = f2tff(v.y * 0.125f);
        sv.z = f2tff(v.z * 0.125f); sv.w = f2tff(v.w * 0.125f);
        *(float4*)&Qs[rr * AT_ST + c4] = sv;
    }

    float oac[2][8][4];
    #pragma unroll
    for (int mt = 0; mt < 2; mt++)
        #pragma unroll
        for (int dt = 0; dt < 8; dt++)
            #pragma unroll
            for (int j = 0; j < 4; j++) oac[mt][dt][j] = 0.f;
    float lsum[2][2] = {{0.f, 0.f}, {0.f, 0.f}};

    for (int n0 = 0; n0 < S_; n0 += 64) {
        __syncthreads();
        #pragma unroll
        for (int it = 0; it < 4; it++) {
            int lin = tid + it * 256;
            int rr = lin >> 4, c4 = (lin & 15) * 4;
            float4 kv = *(const float4*)(Kg + (size_t)(n0 + rr) * D_ + c4);
            float4 vv = *(const float4*)(Vg + (size_t)(n0 + rr) * D_ + c4);
            float4 sk, sv;
            sk.x = f2tff(kv.x); sk.y = f2tff(kv.y); sk.z = f2tff(kv.z); sk.w = f2tff(kv.w);
            sv.x = f2tff(vv.x); sv.y = f2tff(vv.y); sv.z = f2tff(vv.z); sv.w = f2tff(vv.w);
            *(float4*)&Ks[rr * AT_ST + c4] = sk;
            *(float4*)&Vs[rr * AT_ST + c4] = sv;
        }
        if (tid < 64) smf[tid] = mask[b * S_ + n0 + tid] ? 0.f : -1e9f;
        __syncthreads();

        // ---- S = Q K^T ----
        float sc[2][8][4];
        #pragma unroll
        for (int mt = 0; mt < 2; mt++)
            #pragma unroll
            for (int nt = 0; nt < 8; nt++)
                #pragma unroll
                for (int j = 0; j < 4; j++) sc[mt][nt][j] = 0.f;

        #pragma unroll
        for (int ks = 0; ks < 8; ks++) {
            unsigned a[2][4];
            #pragma unroll
            for (int mt = 0; mt < 2; mt++) {
                int row = wrow + mt * 16;
                a[mt][0] = __float_as_uint(Qs[(row + r    ) * AT_ST + ks*8 + c    ]);
                a[mt][1] = __float_as_uint(Qs[(row + r + 8) * AT_ST + ks*8 + c    ]);
                a[mt][2] = __float_as_uint(Qs[(row + r    ) * AT_ST + ks*8 + c + 4]);
                a[mt][3] = __float_as_uint(Qs[(row + r + 8) * AT_ST + ks*8 + c + 4]);
            }
            #pragma unroll
            for (int nt = 0; nt < 8; nt++) {
                unsigned bf[2];
                bf[0] = __float_as_uint(Ks[(nt*8 + r) * AT_ST + ks*8 + c    ]);
                bf[1] = __float_as_uint(Ks[(nt*8 + r) * AT_ST + ks*8 + c + 4]);
                mma8(sc[0][nt], a[0], bf);
                mma8(sc[1][nt], a[1], bf);
            }
        }

        // ---- exp (poly, FMA pipe), accumulate row sums, truncate to tf32 ----
        #pragma unroll
        for (int nt = 0; nt < 8; nt++) {
            float mf0 = smf[nt*8 + 2*c];
            float mf1 = smf[nt*8 + 2*c + 1];
            #pragma unroll
            for (int mt = 0; mt < 2; mt++) {
                float e0 = tf_trunc(exp_fast(fminf(fmaxf(sc[mt][nt][0] + mf0, -80.f), 60.f)));
                float e1 = tf_trunc(exp_fast(fminf(fmaxf(sc[mt][nt][1] + mf1, -80.f), 60.f)));
                float e2 = tf_trunc(exp_fast(fminf(fmaxf(sc[mt][nt][2] + mf0, -80.f), 60.f)));
                float e3 = tf_trunc(exp_fast(fminf(fmaxf(sc[mt][nt][3] + mf1, -80.f), 60.f)));
                lsum[mt][0] += e0 + e1;
                lsum[mt][1] += e2 + e3;
                sc[mt][nt][0] = e0; sc[mt][nt][1] = e1;
                sc[mt][nt][2] = e2; sc[mt][nt][3] = e3;
            }
        }

        // ---- P to smem (warp-private rows) ----
        #pragma unroll
        for (int mt = 0; mt < 2; mt++) {
            int row = wrow + mt * 16;
            #pragma unroll
            for (int nt = 0; nt < 8; nt++) {
                *(float2*)&Ps[(row + r    ) * AT_ST + nt*8 + 2*c] =
                    make_float2(sc[mt][nt][0], sc[mt][nt][1]);
                *(float2*)&Ps[(row + r + 8) * AT_ST + nt*8 + 2*c] =
                    make_float2(sc[mt][nt][2], sc[mt][nt][3]);
            }
        }
        __syncwarp();

        // ---- O += P V ----
        #pragma unroll
        for (int ks = 0; ks < 8; ks++) {
            unsigned a[2][4];
            #pragma unroll
            for (int mt = 0; mt < 2; mt++) {
                int row = wrow + mt * 16;
                a[mt][0] = __float_as_uint(Ps[(row + r    ) * AT_ST + ks*8 + c    ]);
                a[mt][1] = __float_as_uint(Ps[(row + r + 8) * AT_ST + ks*8 + c    ]);
                a[mt][2] = __float_as_uint(Ps[(row + r    ) * AT_ST + ks*8 + c + 4]);
                a[mt][3] = __float_as_uint(Ps[(row + r + 8) * AT_ST + ks*8 + c + 4]);
            }
            #pragma unroll
            for (int dt = 0; dt < 8; dt++) {
                unsigned bf[2];
                bf[0] = __float_as_uint(Vs[(ks*8 + c    ) * AT_ST + dt*8 + r]);
                bf[1] = __float_as_uint(Vs[(ks*8 + c + 4) * AT_ST + dt*8 + r]);
                mma8(oac[0][dt], a[0], bf);
                mma8(oac[1][dt], a[1], bf);
            }
        }
    }

    // ---- epilogue: normalize rows, fused mean via atomics ----
    #pragma unroll
    for (int mt = 0; mt < 2; mt++)
        #pragma unroll
        for (int j = 0; j < 2; j++) {
            float v = lsum[mt][j];
            v += __shfl_xor_sync(0xffffffffu, v, 1);
            v += __shfl_xor_sync(0xffffffffu, v, 2);
            lsum[mt][j] = 1.f / v;
        }

    const int h = bh & 15;
    #pragma unroll
    for (int dt = 0; dt < 8; dt++) {
        float p0 = oac[0][dt][0]*lsum[0][0] + oac[0][dt][2]*lsum[0][1]
                 + oac[1][dt][0]*lsum[1][0] + oac[1][dt][2]*lsum[1][1];
        float p1 = oac[0][dt][1]*lsum[0][0] + oac[0][dt][3]*lsum[0][1]
                 + oac[1][dt][1]*lsum[1][0] + oac[1][dt][3]*lsum[1][1];
        p0 += __shfl_xor_sync(0xffffffffu, p0, 4);
        p0 += __shfl_xor_sync(0xffffffffu, p0, 8);
        p0 += __shfl_xor_sync(0xffffffffu, p0, 16);
        p1 += __shfl_xor_sync(0xffffffffu, p1, 4);
        p1 += __shfl_xor_sync(0xffffffffu, p1, 8);
        p1 += __shfl_xor_sync(0xffffffffu, p1, 16);
        if (lane < 4) {
            atomicAdd(&g_pooled[b*E_ + h*64 + dt*8 + 2*c    ], p0);
            atomicAdd(&g_pooled[b*E_ + h*64 + dt*8 + 2*c + 1], p1);
        }
    }
}

// =====================================================================
// head A: o = (pooled/S) @ Wo^T + bo ; accumulate squared norm
// grid (128, B), 256 thr; warp per output column
// =====================================================================
__global__ __launch_bounds__(256) void headA_kernel(
    const float* __restrict__ Wo, const float* __restrict__ bo)
{
    const int b = blockIdx.y;
    const int n = blockIdx.x * 8 + (threadIdx.x >> 5);
    const int lane = threadIdx.x & 31;
    const float* pr = g_pooled + b * E_;
    const float* wr = Wo + (size_t)n * E_;
    float acc = 0.f;
    #pragma unroll
    for (int i = 0; i < 8; i++) {
        int k = i * 128 + lane * 4;
        float4 w = *(const float4*)(wr + k);
        float4 p = *(const float4*)(pr + k);
        acc += p.x*w.x + p.y*w.y + p.z*w.z + p.w*w.w;
    }
    #pragma unroll
    for (int off = 16; off > 0; off >>= 1)
        acc += __shfl_xor_sync(0xffffffffu, acc, off);
    if (lane == 0) {
        float o = acc * (1.0f / S_) + bo[n];
        g_o[b * E_ + n] = o;
        atomicAdd(&g_nrm[b], o * o);
    }
}

// =====================================================================
// head B: u = o/||o|| - text ; h = relu(u @ W1^T + b1) ; score += h*W2
// grid (64, B), 256 thr; warp per hidden row
// =====================================================================
__global__ __launch_bounds__(256) void headB_kernel(
    const float* __restrict__ text,
    const float* __restrict__ W1, const float* __restrict__ b1,
    const float* __restrict__ W2)
{
    const int b = blockIdx.y;
    const int rr = blockIdx.x * 8 + (threadIdx.x >> 5);
    const int lane = threadIdx.x & 31;
    const float rinv = rsqrtf(g_nrm[b]);
    const float* orow = g_o + b * E_;
    const float* trow = text + b * E_;
    const float* wr = W1 + (size_t)rr * E_;
    float acc = 0.f;
    #pragma unroll
    for (int i = 0; i < 8; i++) {
        int k = i * 128 + lane * 4;
        float4 w = *(const float4*)(wr + k);
        float4 o = *(const float4*)(orow + k);
        float4 t = *(const float4*)(trow + k);
        acc += (o.x*rinv - t.x)*w.x + (o.y*rinv - t.y)*w.y
             + (o.z*rinv - t.z)*w.z + (o.w*rinv - t.w)*w.w;
    }
    #pragma unroll
    for (int off = 16; off > 0; off >>= 1)
        acc += __shfl_xor_sync(0xffffffffu, acc, off);
    if (lane == 0) {
        float hv = fmaxf(acc + b1[rr], 0.f);
        atomicAdd(&g_score[b], hv * W2[rr]);
    }
}

__global__ void headC_kernel(const float* __restrict__ b2, float* __restrict__ out)
{
    int i = threadIdx.x;
    if (i < B_) out[i] = tanhf(g_score[i] + b2[0]);
}

// =====================================================================
// Launch
// =====================================================================
extern "C" void kernel_launch(void* const* d_in, const int* in_sizes, int n_in,
                              void* d_out, int out_size)
{
    (void)in_sizes; (void)n_in; (void)out_size;
    const float* x    = (const float*)d_in[0];
    const int*   mask = (const int*)  d_in[1];
    const float* text = (const float*)d_in[2];
    const float* Wq = (const float*)d_in[3];
    const float* bq = (const float*)d_in[4];
    const float* Wk = (const float*)d_in[5];
    const float* bk = (const float*)d_in[6];
    const float* Wv = (const float*)d_in[7];
    const float* bv = (const float*)d_in[8];
    const float* Wo = (const float*)d_in[9];
    const float* bo = (const float*)d_in[10];
    const float* W1 = (const float*)d_in[11];
    const float* b1 = (const float*)d_in[12];
    const float* W2 = (const float*)d_in[13];
    const float* b2 = (const float*)d_in[14];
    float* out = (float*)d_out;

    cudaFuncSetAttribute(attn_mma, cudaFuncAttributeMaxDynamicSharedMemorySize, ATTN_SMEM);

    zero_kernel<<<16, 256>>>();
    qkv_mma<<<dim3(8, 64, 3), 256>>>(x, Wq, bq, Wk, bk, Wv, bv);
    attn_mma<<<dim3(8, 64), 256, ATTN_SMEM>>>(mask);
    headA_kernel<<<dim3(128, B_), 256>>>(Wo, bo);
    headB_kernel<<<dim3(64, B_), 256>>>(text, W1, b1, W2);
    headC_kernel<<<1, 32>>>(b2, out);
}